// round 1
// baseline (speedup 1.0000x reference)
#include <cuda_runtime.h>
#include <cuda_bf16.h>
#include <math.h>

// Problem constants (fixed by the dataset)
#define BSZ  256
#define HDIM 768
#define H3   2304
#define TSTEPS 128

// Scratch (device globals — no allocation allowed in kernel_launch)
__device__ float g_h[BSZ * HDIM];        // hidden state
__device__ float g_gh[BSZ * H3];         // raw matmul result per step
__device__ float g_delta[BSZ * TSTEPS];  // softplus deltas, [b*T + t]

// ---------------------------------------------------------------------------
// GEMM: C[b, j] = sum_k A[b,k] * W[j,k]   (A: BSZ x HDIM, W: H3 x HDIM)
// 64x64 block tile, BK=16, 256 threads, 4x4 per-thread microtile.
// Grid: (H3/64=36, BSZ/64=4) = 144 blocks.
// ---------------------------------------------------------------------------
__global__ __launch_bounds__(256) void gemm_step_kernel(
    const float* __restrict__ A,   // h_in (context at t=0, g_h after)
    const float* __restrict__ W)   // weight_hh (H3 x HDIM)
{
    __shared__ float As[16][64];
    __shared__ float Bs[16][64];

    const int tid  = threadIdx.x;
    const int brow = blockIdx.y * 64;   // batch rows
    const int bcol = blockIdx.x * 64;   // output cols (gate units)

    const int r  = tid & 63;            // 0..63 row within tile
    const int c4 = tid >> 6;            // 0..3 k-group (of 4)
    const int tx = tid & 15;            // col group
    const int ty = tid >> 4;            // row group

    float acc[4][4];
#pragma unroll
    for (int i = 0; i < 4; i++)
#pragma unroll
        for (int j = 0; j < 4; j++) acc[i][j] = 0.0f;

    const float* Arow = A + (size_t)(brow + r) * HDIM;
    const float* Wrow = W + (size_t)(bcol + r) * HDIM;

    for (int k0 = 0; k0 < HDIM; k0 += 16) {
        float4 av = *reinterpret_cast<const float4*>(Arow + k0 + c4 * 4);
        float4 bv = *reinterpret_cast<const float4*>(Wrow + k0 + c4 * 4);
        As[c4 * 4 + 0][r] = av.x;
        As[c4 * 4 + 1][r] = av.y;
        As[c4 * 4 + 2][r] = av.z;
        As[c4 * 4 + 3][r] = av.w;
        Bs[c4 * 4 + 0][r] = bv.x;
        Bs[c4 * 4 + 1][r] = bv.y;
        Bs[c4 * 4 + 2][r] = bv.z;
        Bs[c4 * 4 + 3][r] = bv.w;
        __syncthreads();

#pragma unroll
        for (int kk = 0; kk < 16; kk++) {
            float4 a = *reinterpret_cast<const float4*>(&As[kk][ty * 4]);
            float4 b = *reinterpret_cast<const float4*>(&Bs[kk][tx * 4]);
            acc[0][0] += a.x * b.x; acc[0][1] += a.x * b.y; acc[0][2] += a.x * b.z; acc[0][3] += a.x * b.w;
            acc[1][0] += a.y * b.x; acc[1][1] += a.y * b.y; acc[1][2] += a.y * b.z; acc[1][3] += a.y * b.w;
            acc[2][0] += a.z * b.x; acc[2][1] += a.z * b.y; acc[2][2] += a.z * b.z; acc[2][3] += a.z * b.w;
            acc[3][0] += a.w * b.x; acc[3][1] += a.w * b.y; acc[3][2] += a.w * b.z; acc[3][3] += a.w * b.w;
        }
        __syncthreads();
    }

#pragma unroll
    for (int i = 0; i < 4; i++) {
        float4 out;
        out.x = acc[i][0]; out.y = acc[i][1]; out.z = acc[i][2]; out.w = acc[i][3];
        *reinterpret_cast<float4*>(&g_gh[(size_t)(brow + ty * 4 + i) * H3 + bcol + tx * 4]) = out;
    }
}

// ---------------------------------------------------------------------------
// Gate kernel: GRU gates + h update + delta = softplus(h_new . fc_w + fc_b)
// One block per batch row, 256 threads, 3 units per thread.
// ---------------------------------------------------------------------------
__device__ __forceinline__ float sigmoidf_(float x) {
    return 1.0f / (1.0f + expf(-x));
}
__device__ __forceinline__ float softplusf_(float x) {
    // stable softplus
    return (x > 0.0f) ? (x + log1pf(expf(-x))) : log1pf(expf(x));
}

__global__ __launch_bounds__(256) void gate_step_kernel(
    const float* __restrict__ h_in,      // context at t=0, g_h after
    const float* __restrict__ bias_ih,
    const float* __restrict__ bias_hh,
    const float* __restrict__ fc_w,
    const float* __restrict__ fc_b,
    int t)
{
    __shared__ float red[256];
    const int b   = blockIdx.x;
    const int tid = threadIdx.x;

    const float* gh_row = &g_gh[(size_t)b * H3];
    const float* h_row  = h_in + (size_t)b * HDIM;
    float*       ho_row = &g_h[(size_t)b * HDIM];

    float local = 0.0f;
#pragma unroll
    for (int u = 0; u < 3; u++) {
        const int j = tid + u * 256;
        float raw_r = gh_row[j];
        float raw_z = gh_row[HDIM + j];
        float raw_n = gh_row[2 * HDIM + j];

        float rg = sigmoidf_(bias_ih[j]            + bias_hh[j]            + raw_r);
        float zg = sigmoidf_(bias_ih[HDIM + j]     + bias_hh[HDIM + j]     + raw_z);
        float ng = tanhf(bias_ih[2 * HDIM + j] + rg * (raw_n + bias_hh[2 * HDIM + j]));

        float hn = (1.0f - zg) * ng + zg * h_row[j];
        ho_row[j] = hn;
        local += hn * fc_w[j];
    }

    red[tid] = local;
    __syncthreads();
#pragma unroll
    for (int s = 128; s >= 32; s >>= 1) {
        if (tid < s) red[tid] += red[tid + s];
        __syncthreads();
    }
    if (tid < 32) {
        float v = red[tid];
#pragma unroll
        for (int off = 16; off > 0; off >>= 1)
            v += __shfl_down_sync(0xFFFFFFFFu, v, off);
        if (tid == 0)
            g_delta[(size_t)b * TSTEPS + t] = softplusf_(v + fc_b[0]);
    }
}

// ---------------------------------------------------------------------------
// Final: cumsum, normalize by cum[n-1], mask, scatter 1.0 at column n+1.
// One block (128 threads) per batch row. Output: (BSZ, TSTEPS + 2)
// ---------------------------------------------------------------------------
__global__ __launch_bounds__(128) void finalize_kernel(
    const int* __restrict__ num_pred,
    float* __restrict__ out)
{
    __shared__ float s[TSTEPS];
    const int b = blockIdx.x;
    const int t = threadIdx.x;

    s[t] = g_delta[(size_t)b * TSTEPS + t];
    __syncthreads();

    // Hillis-Steele inclusive scan
#pragma unroll
    for (int off = 1; off < TSTEPS; off <<= 1) {
        float v = (t >= off) ? s[t - off] : 0.0f;
        __syncthreads();
        s[t] += v;
        __syncthreads();
    }

    const int n = num_pred[b];                     // 1..128
    int idx = n - 1;
    if (idx < 0) idx = 0;
    if (idx > TSTEPS - 1) idx = TSTEPS - 1;
    const float last = s[idx] + 1e-6f;

    float* orow = out + (size_t)b * (TSTEPS + 2);
    float val;
    if (t < n)       val = s[t] / last;
    else if (t == n) val = 1.0f;                   // scatter at column n+1 (== t+1 with t=n)
    else             val = 0.0f;
    orow[t + 1] = val;

    if (t == 0) {
        orow[0] = 0.0f;
        orow[TSTEPS + 1] = (n == TSTEPS) ? 1.0f : 0.0f;
    }
}

// ---------------------------------------------------------------------------
// Launch
// Inputs: 0 context(256,768) 1 weight_ih(unused) 2 weight_hh(2304,768)
//         3 bias_ih(2304) 4 bias_hh(2304) 5 fc_w(768) 6 fc_b(1)
//         7 num_pred_list(256,int32) 8 max_steps
// ---------------------------------------------------------------------------
extern "C" void kernel_launch(void* const* d_in, const int* in_sizes, int n_in,
                              void* d_out, int out_size)
{
    const float* context  = (const float*)d_in[0];
    const float* Whh      = (const float*)d_in[2];
    const float* bias_ih  = (const float*)d_in[3];
    const float* bias_hh  = (const float*)d_in[4];
    const float* fc_w     = (const float*)d_in[5];
    const float* fc_b     = (const float*)d_in[6];
    const int*   num_pred = (const int*)d_in[7];
    float*       out      = (float*)d_out;

    float* h_ptr = nullptr;
    cudaGetSymbolAddress((void**)&h_ptr, g_h);

    dim3 gemm_grid(H3 / 64, BSZ / 64);  // (36, 4)

    for (int t = 0; t < TSTEPS; t++) {
        const float* h_in = (t == 0) ? context : h_ptr;
        gemm_step_kernel<<<gemm_grid, 256>>>(h_in, Whh);
        gate_step_kernel<<<BSZ, 256>>>(h_in, bias_ih, bias_hh, fc_w, fc_b, t);
    }
    finalize_kernel<<<BSZ, 128>>>(num_pred, out);
}

// round 3
// speedup vs baseline: 2.6294x; 2.6294x over previous
#include <cuda_runtime.h>
#include <cuda_bf16.h>
#include <math.h>
#include <stdint.h>

// Problem constants
#define BSZ    256
#define HDIM   768
#define H3     2304
#define TSTEPS 128

// Tiling
#define JT       16               // j-columns per CTA (per gate)
#define NB       48               // MMA N = 3 gates * JT
#define MTILE    64               // batch rows per CTA
#define KCHUNK   64               // K elements per chunk
#define NCHUNKS  (HDIM / KCHUNK)  // 12
#define NTHREADS 128
#define NJB      (HDIM / JT)      // 48 j-blocks

// SMEM layout (bytes). Row stride 72 bf16 = 144B (odd # of 16B units -> conflict-free ldmatrix)
#define SMSTRIDE 144
#define OFF_AH   0
#define OFF_AL   (MTILE * SMSTRIDE)                   // 9216
#define OFF_BH   (2 * MTILE * SMSTRIDE)               // 18432
#define OFF_BL   (2 * MTILE * SMSTRIDE + NB * SMSTRIDE) // 25344
#define BUFBYTES (2 * MTILE * SMSTRIDE + 2 * NB * SMSTRIDE) // 32256
#define SMEM_DYN (2 * BUFBYTES)                       // 64512
#define CSTRIDE  53                                   // fp32 C row stride (gcd(53,32)=1)

// ---------------------------------------------------------------------------
// Device globals
// ---------------------------------------------------------------------------
__device__ __align__(16) float         g_hf[2][BSZ * HDIM];
__device__ __align__(16) __nv_bfloat16 g_hhi[2][BSZ * HDIM];
__device__ __align__(16) __nv_bfloat16 g_hlo[2][BSZ * HDIM];
__device__ __align__(16) __nv_bfloat16 g_whi[H3 * HDIM];
__device__ __align__(16) __nv_bfloat16 g_wlo[H3 * HDIM];
__device__ float g_dotp[TSTEPS * NJB * BSZ];   // deterministic fc partials

// ---------------------------------------------------------------------------
// PTX helpers (baseline sm_80+ features only — NO tcgen05)
// ---------------------------------------------------------------------------
__device__ __forceinline__ uint32_t smem_u32(const void* p) {
    uint32_t a;
    asm("{ .reg .u64 t; cvta.to.shared.u64 t, %1; cvt.u32.u64 %0, t; }"
        : "=r"(a) : "l"(p));
    return a;
}
__device__ __forceinline__ void cp16(uint32_t d, const void* s) {
    asm volatile("cp.async.cg.shared.global [%0], [%1], 16;" :: "r"(d), "l"(s));
}
__device__ __forceinline__ void cp_commit() {
    asm volatile("cp.async.commit_group;" ::: "memory");
}
template <int N>
__device__ __forceinline__ void cp_wait() {
    asm volatile("cp.async.wait_group %0;" :: "n"(N) : "memory");
}
__device__ __forceinline__ void ldsm_x4(uint32_t* r, uint32_t a) {
    asm volatile("ldmatrix.sync.aligned.m8n8.x4.shared.b16 {%0,%1,%2,%3}, [%4];"
                 : "=r"(r[0]), "=r"(r[1]), "=r"(r[2]), "=r"(r[3]) : "r"(a));
}
__device__ __forceinline__ void ldsm_x2(uint32_t* r, uint32_t a) {
    asm volatile("ldmatrix.sync.aligned.m8n8.x2.shared.b16 {%0,%1}, [%2];"
                 : "=r"(r[0]), "=r"(r[1]) : "r"(a));
}
__device__ __forceinline__ void mma_bf16(float* c, const uint32_t* a, const uint32_t* b) {
    asm volatile(
        "mma.sync.aligned.m16n8k16.row.col.f32.bf16.bf16.f32 "
        "{%0,%1,%2,%3}, {%4,%5,%6,%7}, {%8,%9}, {%0,%1,%2,%3};"
        : "+f"(c[0]), "+f"(c[1]), "+f"(c[2]), "+f"(c[3])
        : "r"(a[0]), "r"(a[1]), "r"(a[2]), "r"(a[3]), "r"(b[0]), "r"(b[1]));
}

// ---------------------------------------------------------------------------
// Prep kernels: hi/lo bf16 splits of W and h0
// ---------------------------------------------------------------------------
__global__ void prep_w_kernel(const float* __restrict__ W) {
    int i = blockIdx.x * blockDim.x + threadIdx.x;
    if (i < H3 * HDIM) {
        float v = W[i];
        __nv_bfloat16 hi = __float2bfloat16_rn(v);
        g_whi[i] = hi;
        g_wlo[i] = __float2bfloat16_rn(v - __bfloat162float(hi));
    }
}
__global__ void prep_h_kernel(const float* __restrict__ ctx) {
    int i = blockIdx.x * blockDim.x + threadIdx.x;
    if (i < BSZ * HDIM) {
        float v = ctx[i];
        g_hf[0][i] = v;
        __nv_bfloat16 hi = __float2bfloat16_rn(v);
        g_hhi[0][i] = hi;
        g_hlo[0][i] = __float2bfloat16_rn(v - __bfloat162float(hi));
    }
}

// ---------------------------------------------------------------------------
// Fused step: gh = h @ Whh^T (split-bf16 HMMA, 3 terms) + gates + h update
// Grid: (48, 4), 128 threads (4 warps), warp tile 32x24.
// ---------------------------------------------------------------------------
__global__ __launch_bounds__(NTHREADS) void step_kernel(
    const float* __restrict__ bias_ih,
    const float* __restrict__ bias_hh,
    const float* __restrict__ fc_w,
    int t)
{
    extern __shared__ __align__(16) uint8_t smem[];
    const uint32_t sbase = smem_u32(smem);

    const int tid    = threadIdx.x;
    const int lane   = tid & 31;
    const int wid    = tid >> 5;
    const int warp_m = (wid & 1) * 32;
    const int warp_n = (wid >> 1) * 24;
    const int j0     = blockIdx.x * JT;
    const int brow   = blockIdx.y * MTILE;
    const int rp     = t & 1;
    const int wp     = rp ^ 1;

    const __nv_bfloat16* __restrict__ hhi = g_hhi[rp];
    const __nv_bfloat16* __restrict__ hlo = g_hlo[rp];

    float acc[2][3][4];
#pragma unroll
    for (int mi = 0; mi < 2; mi++)
#pragma unroll
        for (int ni = 0; ni < 3; ni++)
#pragma unroll
            for (int q = 0; q < 4; q++) acc[mi][ni][q] = 0.0f;

    // ---- async stage of one K-chunk into buffer (ck&1) ----
    auto issue = [&](int ck) {
        const int k0 = ck * KCHUNK;
        const uint32_t base = sbase + (uint32_t)(ck & 1) * BUFBYTES;
#pragma unroll
        for (int idx = tid; idx < MTILE * 8; idx += NTHREADS) {   // 4 iters
            int r = idx >> 3, cg = idx & 7;
            uint32_t off = r * SMSTRIDE + cg * 16;
            size_t so = (size_t)(brow + r) * HDIM + k0 + cg * 8;
            cp16(base + OFF_AH + off, hhi + so);
            cp16(base + OFF_AL + off, hlo + so);
        }
#pragma unroll
        for (int idx = tid; idx < NB * 8; idx += NTHREADS) {      // 3 iters
            int rr = idx >> 3, cg = idx & 7;
            uint32_t off = rr * SMSTRIDE + cg * 16;
            int g = rr >> 4, jj = rr & 15;
            size_t so = (size_t)(g * HDIM + j0 + jj) * HDIM + k0 + cg * 8;
            cp16(base + OFF_BH + off, g_whi + so);
            cp16(base + OFF_BL + off, g_wlo + so);
        }
        cp_commit();
    };

    auto compute = [&](int ck) {
        const uint32_t base = sbase + (uint32_t)(ck & 1) * BUFBYTES;
        const uint32_t arow = (uint32_t)(warp_m + (lane & 15)) * SMSTRIDE +
                              ((lane >> 4) & 1) * 16;
        const uint32_t brow_a = (uint32_t)(warp_n + (lane & 7)) * SMSTRIDE +
                                ((lane >> 3) & 1) * 16;
#pragma unroll
        for (int ks = 0; ks < KCHUNK / 16; ks++) {
            const uint32_t kb = ks * 32;
            uint32_t ah[2][4], al[2][4], bh[3][2], bl[3][2];
#pragma unroll
            for (int mi = 0; mi < 2; mi++) {
                uint32_t a = base + OFF_AH + arow + mi * (16 * SMSTRIDE) + kb;
                ldsm_x4(ah[mi], a);
                ldsm_x4(al[mi], a + (OFF_AL - OFF_AH));
            }
#pragma unroll
            for (int ni = 0; ni < 3; ni++) {
                uint32_t a = base + OFF_BH + brow_a + ni * (8 * SMSTRIDE) + kb;
                ldsm_x2(bh[ni], a);
                ldsm_x2(bl[ni], a + (OFF_BL - OFF_BH));
            }
#pragma unroll
            for (int mi = 0; mi < 2; mi++)
#pragma unroll
                for (int ni = 0; ni < 3; ni++) {
                    mma_bf16(acc[mi][ni], ah[mi], bh[ni]);
                    mma_bf16(acc[mi][ni], ah[mi], bl[ni]);
                    mma_bf16(acc[mi][ni], al[mi], bh[ni]);
                }
        }
    };

    // ---- pipelined K loop ----
    issue(0);
    for (int ck = 0; ck < NCHUNKS; ck++) {
        if (ck + 1 < NCHUNKS) { issue(ck + 1); cp_wait<1>(); }
        else                  { cp_wait<0>(); }
        __syncthreads();
        compute(ck);
        __syncthreads();
    }

    // ---- write C to SMEM (aliases buffer 0) ----
    float* Csm = (float*)smem;
    {
        const int r0 = lane >> 2, cp = (lane & 3) * 2;
#pragma unroll
        for (int mi = 0; mi < 2; mi++)
#pragma unroll
            for (int ni = 0; ni < 3; ni++) {
                int row = warp_m + mi * 16 + r0;
                int col = warp_n + ni * 8 + cp;
                Csm[row * CSTRIDE + col]           = acc[mi][ni][0];
                Csm[row * CSTRIDE + col + 1]       = acc[mi][ni][1];
                Csm[(row + 8) * CSTRIDE + col]     = acc[mi][ni][2];
                Csm[(row + 8) * CSTRIDE + col + 1] = acc[mi][ni][3];
            }
    }
    __syncthreads();

    // ---- gate epilogue: one thread per batch row ----
    if (tid < MTILE) {
        const int b = brow + tid;
        const float* __restrict__ hof = g_hf[rp] + (size_t)b * HDIM;
        float* __restrict__ hnf = g_hf[wp] + (size_t)b * HDIM;
        __nv_bfloat16* __restrict__ hih = g_hhi[wp] + (size_t)b * HDIM;
        __nv_bfloat16* __restrict__ hil = g_hlo[wp] + (size_t)b * HDIM;
        const float* crow = Csm + tid * CSTRIDE;

        float part = 0.0f;
#pragma unroll
        for (int jj = 0; jj < JT; jj++) {
            const int j = j0 + jj;
            float rawr = crow[jj];
            float rawz = crow[JT + jj];
            float rawn = crow[2 * JT + jj];

            float rg = 1.0f / (1.0f + expf(-(bias_ih[j] + bias_hh[j] + rawr)));
            float zg = 1.0f / (1.0f + expf(-(bias_ih[HDIM + j] + bias_hh[HDIM + j] + rawz)));
            float ng = tanhf(bias_ih[2 * HDIM + j] + rg * (rawn + bias_hh[2 * HDIM + j]));
            float hn = (1.0f - zg) * ng + zg * hof[j];

            hnf[j] = hn;
            __nv_bfloat16 hi = __float2bfloat16_rn(hn);
            hih[j] = hi;
            hil[j] = __float2bfloat16_rn(hn - __bfloat162float(hi));
            part += hn * fc_w[j];
        }
        g_dotp[(size_t)t * NJB * BSZ + blockIdx.x * BSZ + b] = part;
    }
}

// ---------------------------------------------------------------------------
// Finalize: dot = sum of 48 partials (fixed order), softplus, scan, normalize
// ---------------------------------------------------------------------------
__device__ __forceinline__ float softplusf_(float x) {
    return (x > 0.0f) ? (x + log1pf(expf(-x))) : log1pf(expf(x));
}

__global__ __launch_bounds__(TSTEPS) void finalize_kernel(
    const int* __restrict__ num_pred,
    const float* __restrict__ fc_b,
    float* __restrict__ out)
{
    __shared__ float s[TSTEPS];
    const int b = blockIdx.x;
    const int t = threadIdx.x;

    float dot = fc_b[0];
    const float* p = g_dotp + (size_t)t * NJB * BSZ + b;
#pragma unroll
    for (int jb = 0; jb < NJB; jb++) dot += p[jb * BSZ];
    s[t] = softplusf_(dot);
    __syncthreads();

#pragma unroll
    for (int off = 1; off < TSTEPS; off <<= 1) {
        float v = (t >= off) ? s[t - off] : 0.0f;
        __syncthreads();
        s[t] += v;
        __syncthreads();
    }

    const int n = num_pred[b];
    int idx = n - 1;
    if (idx < 0) idx = 0;
    if (idx > TSTEPS - 1) idx = TSTEPS - 1;
    const float last = s[idx] + 1e-6f;

    float* orow = out + (size_t)b * (TSTEPS + 2);
    float val;
    if (t < n)       val = s[t] / last;
    else if (t == n) val = 1.0f;
    else             val = 0.0f;
    orow[t + 1] = val;

    if (t == 0) {
        orow[0] = 0.0f;
        orow[TSTEPS + 1] = (n == TSTEPS) ? 1.0f : 0.0f;
    }
}

// ---------------------------------------------------------------------------
// Launch. Inputs: 0 context 1 weight_ih(unused) 2 weight_hh 3 bias_ih
//                 4 bias_hh 5 fc_w 6 fc_b 7 num_pred_list 8 max_steps
// ---------------------------------------------------------------------------
extern "C" void kernel_launch(void* const* d_in, const int* in_sizes, int n_in,
                              void* d_out, int out_size)
{
    const float* context  = (const float*)d_in[0];
    const float* Whh      = (const float*)d_in[2];
    const float* bias_ih  = (const float*)d_in[3];
    const float* bias_hh  = (const float*)d_in[4];
    const float* fc_w     = (const float*)d_in[5];
    const float* fc_b     = (const float*)d_in[6];
    const int*   num_pred = (const int*)d_in[7];
    float*       out      = (float*)d_out;

    static bool attr_set = false;
    if (!attr_set) {
        cudaFuncSetAttribute(step_kernel,
                             cudaFuncAttributeMaxDynamicSharedMemorySize, SMEM_DYN);
        attr_set = true;
    }

    prep_w_kernel<<<(H3 * HDIM + 255) / 256, 256>>>(Whh);
    prep_h_kernel<<<(BSZ * HDIM + 255) / 256, 256>>>(context);

    dim3 grid(NJB, BSZ / MTILE);  // (48, 4) = 192 CTAs
    for (int t = 0; t < TSTEPS; t++) {
        step_kernel<<<grid, NTHREADS, SMEM_DYN>>>(bias_ih, bias_hh, fc_w, t);
    }
    finalize_kernel<<<BSZ, TSTEPS>>>(num_pred, fc_b, out);
}

// round 4
// speedup vs baseline: 3.0174x; 1.1476x over previous
#include <cuda_runtime.h>
#include <cuda_bf16.h>
#include <math.h>
#include <stdint.h>

// Problem constants
#define BSZ    256
#define HDIM   768
#define H3     2304
#define TSTEPS 128

// Tiling
#define JT       16               // j-columns per CTA (per gate)
#define NB       48               // 3 gates * JT rows of W per CTA
#define MTILE    128              // batch rows per CTA
#define KCHUNK   64               // K elems per A chunk
#define NCHUNKS  (HDIM / KCHUNK)  // 12
#define NTHREADS 256
#define NJB      (HDIM / JT)      // 48
#define NCTA     96               // 48 x 2, all resident (1 CTA/SM)

// Dynamic SMEM layout (bytes)
//   W resident: [part(2)][chunk(12)][row(48)][128B] with SW128 swizzle
//   A chunks:   [buf(2)][part(2)][row(128)][128B]  with SW128 swizzle
#define WPART    (NCHUNKS * NB * 128)          // 73728
#define AOFF     (2 * WPART)                   // 147456
#define APART    (MTILE * 128)                 // 16384
#define ABUF     (2 * APART)                   // 32768
#define SMEM_DYN (AOFF + 2 * ABUF)             // 212992
#define CSTRIDE  49                            // fp32 C row stride in epilogue

// ---------------------------------------------------------------------------
// Device globals
// ---------------------------------------------------------------------------
__device__ __align__(16) __nv_bfloat16 g_hhi[2][BSZ * HDIM];
__device__ __align__(16) __nv_bfloat16 g_hlo[2][BSZ * HDIM];
__device__ __align__(16) __nv_bfloat16 g_whi[H3 * HDIM];
__device__ __align__(16) __nv_bfloat16 g_wlo[H3 * HDIM];
__device__ float    g_dotp[TSTEPS * NJB * BSZ];
__device__ unsigned g_bar;

// ---------------------------------------------------------------------------
// PTX helpers (baseline sm_80/90 features only — NO tcgen05)
// ---------------------------------------------------------------------------
__device__ __forceinline__ uint32_t smem_u32(const void* p) {
    uint32_t a;
    asm("{ .reg .u64 t; cvta.to.shared.u64 t, %1; cvt.u32.u64 %0, t; }"
        : "=r"(a) : "l"(p));
    return a;
}
__device__ __forceinline__ void cp16(uint32_t d, const void* s) {
    asm volatile("cp.async.cg.shared.global [%0], [%1], 16;" :: "r"(d), "l"(s));
}
__device__ __forceinline__ void cp_commit() {
    asm volatile("cp.async.commit_group;" ::: "memory");
}
template <int N>
__device__ __forceinline__ void cp_wait() {
    asm volatile("cp.async.wait_group %0;" :: "n"(N) : "memory");
}
__device__ __forceinline__ void ldsm_x4(uint32_t* r, uint32_t a) {
    asm volatile("ldmatrix.sync.aligned.m8n8.x4.shared.b16 {%0,%1,%2,%3}, [%4];"
                 : "=r"(r[0]), "=r"(r[1]), "=r"(r[2]), "=r"(r[3]) : "r"(a));
}
__device__ __forceinline__ void ldsm_x2(uint32_t* r, uint32_t a) {
    asm volatile("ldmatrix.sync.aligned.m8n8.x2.shared.b16 {%0,%1}, [%2];"
                 : "=r"(r[0]), "=r"(r[1]) : "r"(a));
}
__device__ __forceinline__ void mma_bf16(float* c, const uint32_t* a, const uint32_t* b) {
    asm volatile(
        "mma.sync.aligned.m16n8k16.row.col.f32.bf16.bf16.f32 "
        "{%0,%1,%2,%3}, {%4,%5,%6,%7}, {%8,%9}, {%0,%1,%2,%3};"
        : "+f"(c[0]), "+f"(c[1]), "+f"(c[2]), "+f"(c[3])
        : "r"(a[0]), "r"(a[1]), "r"(a[2]), "r"(a[3]), "r"(b[0]), "r"(b[1]));
}
#define SW128(o) ((o) ^ (((o) >> 3) & 0x70))

// ---------------------------------------------------------------------------
// Prep kernels
// ---------------------------------------------------------------------------
__global__ void prep_w_kernel(const float* __restrict__ W) {
    int i = blockIdx.x * blockDim.x + threadIdx.x;
    if (i < H3 * HDIM) {
        float v = W[i];
        __nv_bfloat16 hi = __float2bfloat16_rn(v);
        g_whi[i] = hi;
        g_wlo[i] = __float2bfloat16_rn(v - __bfloat162float(hi));
    }
}
__global__ void prep_h_kernel(const float* __restrict__ ctx) {
    int i = blockIdx.x * blockDim.x + threadIdx.x;
    if (i == 0) g_bar = 0u;
    if (i < BSZ * HDIM) {
        float v = ctx[i];
        __nv_bfloat16 hi = __float2bfloat16_rn(v);
        g_hhi[0][i] = hi;
        g_hlo[0][i] = __float2bfloat16_rn(v - __bfloat162float(hi));
    }
}

// ---------------------------------------------------------------------------
// Grid barrier (all NCTA CTAs are guaranteed co-resident: 96 CTAs, 1/SM)
// ---------------------------------------------------------------------------
__device__ __forceinline__ void grid_barrier(unsigned target) {
    __syncthreads();
    if (threadIdx.x == 0) {
        __threadfence();
        atomicAdd(&g_bar, 1u);
        unsigned v;
        do { v = *(volatile unsigned*)&g_bar; } while (v < target);
        __threadfence();
    }
    __syncthreads();
}

// ---------------------------------------------------------------------------
// Persistent kernel: all 128 GRU steps.
// Grid (48, 2), 256 threads = 8 warps, warp tile 32x24 over CTA tile 128x48.
// ---------------------------------------------------------------------------
__global__ __launch_bounds__(NTHREADS, 1) void persist_kernel(
    const float* __restrict__ context,
    const float* __restrict__ bias_ih,
    const float* __restrict__ bias_hh,
    const float* __restrict__ fc_w)
{
    extern __shared__ __align__(16) uint8_t smem[];
    __shared__ float sbr[JT], sbz[JT], sbni[JT], sbnh[JT], sfw[JT];

    const uint32_t sbase = smem_u32(smem);
    const int tid    = threadIdx.x;
    const int lane   = tid & 31;
    const int wid    = tid >> 5;
    const int warp_m = (wid & 3) * 32;
    const int warp_n = (wid >> 2) * 24;
    const int jb     = blockIdx.x;
    const int j0     = jb * JT;
    const int brow   = blockIdx.y * MTILE;

    // ---- stage resident W (hi+lo) into SMEM, SW128 swizzled ----
    for (int idx = tid; idx < NCHUNKS * NB * 8; idx += NTHREADS) {
        int ck  = idx / (NB * 8);
        int rem = idx - ck * (NB * 8);
        int r   = rem >> 3, cg = rem & 7;
        int wrow = (r >> 4) * HDIM + j0 + (r & 15);
        size_t so = (size_t)wrow * HDIM + ck * KCHUNK + cg * 8;
        uint32_t dst = (uint32_t)(ck * (NB * 128)) + SW128((uint32_t)(r * 128 + cg * 16));
        cp16(sbase + dst,         g_whi + so);
        cp16(sbase + WPART + dst, g_wlo + so);
    }
    cp_commit();

    // ---- per-CTA bias/fc constants ----
    if (tid < JT) {
        int j = j0 + tid;
        sbr[tid]  = bias_ih[j] + bias_hh[j];
        sbz[tid]  = bias_ih[HDIM + j] + bias_hh[HDIM + j];
        sbni[tid] = bias_ih[2 * HDIM + j];
        sbnh[tid] = bias_hh[2 * HDIM + j];
        sfw[tid]  = fc_w[j];
    }

    // ---- fp32 h lives in registers: thread t<128 owns row brow+t, cols j0..j0+15
    float hreg[JT];
    if (tid < MTILE) {
        const float* crow = context + (size_t)(brow + tid) * HDIM + j0;
#pragma unroll
        for (int jj = 0; jj < JT; jj++) hreg[jj] = crow[jj];
    }
    __syncthreads();

    unsigned bar_target = 0;
    for (int t = 0; t < TSTEPS; t++) {
        const int rp = t & 1;
        const int wp = rp ^ 1;
        const __nv_bfloat16* __restrict__ hhi = g_hhi[rp];
        const __nv_bfloat16* __restrict__ hlo = g_hlo[rp];

        float acc[2][3][4];
#pragma unroll
        for (int mi = 0; mi < 2; mi++)
#pragma unroll
            for (int ni = 0; ni < 3; ni++)
#pragma unroll
                for (int q = 0; q < 4; q++) acc[mi][ni][q] = 0.0f;

        auto issueA = [&](int ck) {
            const int k0 = ck * KCHUNK;
            const uint32_t abase = sbase + AOFF + (uint32_t)(ck & 1) * ABUF;
#pragma unroll
            for (int idx = tid; idx < MTILE * 8; idx += NTHREADS) {  // 4 iters
                int r = idx >> 3, cg = idx & 7;
                uint32_t off = SW128((uint32_t)(r * 128 + cg * 16));
                size_t so = (size_t)(brow + r) * HDIM + k0 + cg * 8;
                cp16(abase + off,         hhi + so);
                cp16(abase + APART + off, hlo + so);
            }
            cp_commit();
        };

        auto compute = [&](int ck) {
            const uint32_t abase = sbase + AOFF + (uint32_t)(ck & 1) * ABUF;
            const uint32_t wbase = sbase + (uint32_t)(ck * (NB * 128));
#pragma unroll
            for (int ks = 0; ks < KCHUNK / 16; ks++) {
                const uint32_t kb = ks * 32;
                uint32_t ah[2][4], al[2][4], bh[3][2], bl[3][2];
#pragma unroll
                for (int mi = 0; mi < 2; mi++) {
                    uint32_t off = SW128(
                        (uint32_t)((warp_m + mi * 16 + (lane & 15)) * 128) + kb +
                        ((lane >> 4) & 1) * 16);
                    ldsm_x4(ah[mi], abase + off);
                    ldsm_x4(al[mi], abase + APART + off);
                }
#pragma unroll
                for (int ni = 0; ni < 3; ni++) {
                    uint32_t off = SW128(
                        (uint32_t)((warp_n + ni * 8 + (lane & 7)) * 128) + kb +
                        ((lane >> 3) & 1) * 16);
                    ldsm_x2(bh[ni], wbase + off);
                    ldsm_x2(bl[ni], wbase + WPART + off);
                }
#pragma unroll
                for (int mi = 0; mi < 2; mi++)
#pragma unroll
                    for (int ni = 0; ni < 3; ni++) {
                        mma_bf16(acc[mi][ni], ah[mi], bh[ni]);
                        mma_bf16(acc[mi][ni], ah[mi], bl[ni]);
                        mma_bf16(acc[mi][ni], al[mi], bh[ni]);
                    }
            }
        };

        // pipelined K loop (W groups from t=0 drain at first wait)
        issueA(0);
        for (int ck = 0; ck < NCHUNKS; ck++) {
            if (ck + 1 < NCHUNKS) { issueA(ck + 1); cp_wait<1>(); }
            else                  { cp_wait<0>(); }
            __syncthreads();
            compute(ck);
            __syncthreads();
        }

        // ---- C to SMEM (aliases A buffers; safe: all computes done) ----
        float* Csm = (float*)(smem + AOFF);
        {
            const int r0 = lane >> 2, cpn = (lane & 3) * 2;
#pragma unroll
            for (int mi = 0; mi < 2; mi++)
#pragma unroll
                for (int ni = 0; ni < 3; ni++) {
                    int row = warp_m + mi * 16 + r0;
                    int col = warp_n + ni * 8 + cpn;
                    Csm[row * CSTRIDE + col]           = acc[mi][ni][0];
                    Csm[row * CSTRIDE + col + 1]       = acc[mi][ni][1];
                    Csm[(row + 8) * CSTRIDE + col]     = acc[mi][ni][2];
                    Csm[(row + 8) * CSTRIDE + col + 1] = acc[mi][ni][3];
                }
        }
        __syncthreads();

        // ---- gate epilogue: one thread per batch row ----
        if (tid < MTILE) {
            const int b = brow + tid;
            __nv_bfloat16* __restrict__ hih = g_hhi[wp] + (size_t)b * HDIM + j0;
            __nv_bfloat16* __restrict__ hil = g_hlo[wp] + (size_t)b * HDIM + j0;
            const float* crow = Csm + tid * CSTRIDE;

            float part = 0.0f;
#pragma unroll
            for (int jj = 0; jj < JT; jj++) {
                float rawr = crow[jj];
                float rawz = crow[JT + jj];
                float rawn = crow[2 * JT + jj];

                float rg = 1.0f / (1.0f + expf(-(sbr[jj] + rawr)));
                float zg = 1.0f / (1.0f + expf(-(sbz[jj] + rawz)));
                float ng = tanhf(sbni[jj] + rg * (rawn + sbnh[jj]));
                float hn = (1.0f - zg) * ng + zg * hreg[jj];

                hreg[jj] = hn;
                __nv_bfloat16 hi = __float2bfloat16_rn(hn);
                hih[jj] = hi;
                hil[jj] = __float2bfloat16_rn(hn - __bfloat162float(hi));
                part += hn * sfw[jj];
            }
            g_dotp[(size_t)t * NJB * BSZ + jb * BSZ + b] = part;
        }
        __syncthreads();   // protect Csm/A-buffer reuse by next step's issueA(0)

        bar_target += NCTA;
        if (t + 1 < TSTEPS) grid_barrier(bar_target);
    }
}

// ---------------------------------------------------------------------------
// Finalize: dot = fixed-order sum of 48 partials, softplus, scan, normalize
// ---------------------------------------------------------------------------
__device__ __forceinline__ float softplusf_(float x) {
    return (x > 0.0f) ? (x + log1pf(expf(-x))) : log1pf(expf(x));
}

__global__ __launch_bounds__(TSTEPS) void finalize_kernel(
    const int* __restrict__ num_pred,
    const float* __restrict__ fc_b,
    float* __restrict__ out)
{
    __shared__ float s[TSTEPS];
    const int b = blockIdx.x;
    const int t = threadIdx.x;

    float dot = fc_b[0];
    const float* p = g_dotp + (size_t)t * NJB * BSZ + b;
#pragma unroll
    for (int jbk = 0; jbk < NJB; jbk++) dot += p[jbk * BSZ];
    s[t] = softplusf_(dot);
    __syncthreads();

#pragma unroll
    for (int off = 1; off < TSTEPS; off <<= 1) {
        float v = (t >= off) ? s[t - off] : 0.0f;
        __syncthreads();
        s[t] += v;
        __syncthreads();
    }

    const int n = num_pred[b];
    int idx = n - 1;
    if (idx < 0) idx = 0;
    if (idx > TSTEPS - 1) idx = TSTEPS - 1;
    const float last = s[idx] + 1e-6f;

    float* orow = out + (size_t)b * (TSTEPS + 2);
    float val;
    if (t < n)       val = s[t] / last;
    else if (t == n) val = 1.0f;
    else             val = 0.0f;
    orow[t + 1] = val;

    if (t == 0) {
        orow[0] = 0.0f;
        orow[TSTEPS + 1] = (n == TSTEPS) ? 1.0f : 0.0f;
    }
}

// ---------------------------------------------------------------------------
// Launch. Inputs: 0 context 1 weight_ih(unused) 2 weight_hh 3 bias_ih
//                 4 bias_hh 5 fc_w 6 fc_b 7 num_pred_list 8 max_steps
// ---------------------------------------------------------------------------
extern "C" void kernel_launch(void* const* d_in, const int* in_sizes, int n_in,
                              void* d_out, int out_size)
{
    const float* context  = (const float*)d_in[0];
    const float* Whh      = (const float*)d_in[2];
    const float* bias_ih  = (const float*)d_in[3];
    const float* bias_hh  = (const float*)d_in[4];
    const float* fc_w     = (const float*)d_in[5];
    const float* fc_b     = (const float*)d_in[6];
    const int*   num_pred = (const int*)d_in[7];
    float*       out      = (float*)d_out;

    static bool attr_set = false;
    if (!attr_set) {
        cudaFuncSetAttribute(persist_kernel,
                             cudaFuncAttributeMaxDynamicSharedMemorySize, SMEM_DYN);
        attr_set = true;
    }

    prep_w_kernel<<<(H3 * HDIM + 255) / 256, 256>>>(Whh);
    prep_h_kernel<<<(BSZ * HDIM + 255) / 256, 256>>>(context);

    dim3 grid(NJB, BSZ / MTILE);  // (48, 2) = 96 CTAs, 1 per SM
    persist_kernel<<<grid, NTHREADS, SMEM_DYN>>>(context, bias_ih, bias_hh, fc_w);

    finalize_kernel<<<BSZ, TSTEPS>>>(num_pred, fc_b, out);
}

// round 5
// speedup vs baseline: 3.3301x; 1.1036x over previous
#include <cuda_runtime.h>
#include <cuda_bf16.h>
#include <math.h>
#include <stdint.h>

// Problem constants
#define BSZ    256
#define HDIM   768
#define H3     2304
#define TSTEPS 128

// Tiling
#define JT       16               // j-columns per CTA (per gate)
#define NB       48               // 3 gates * JT rows of W per CTA
#define MTILE    128              // batch rows per CTA
#define KCHUNK   64               // K elems per A chunk
#define NCHUNKS  (HDIM / KCHUNK)  // 12
#define NTHREADS 512              // 16 warps, 4 per SMSP
#define NJB      (HDIM / JT)      // 48
#define NCTA     96               // 48 x 2, all resident (1 CTA/SM)

// Dynamic SMEM layout (bytes)
#define WPART    (NCHUNKS * NB * 128)          // 73728
#define AOFF     (2 * WPART)                   // 147456
#define APART    (MTILE * 128)                 // 16384
#define ABUF     (2 * APART)                   // 32768
#define SMEM_DYN (AOFF + 2 * ABUF)             // 212992
#define CSTRIDE  49                            // fp32 C row stride in epilogue

// ---------------------------------------------------------------------------
// Device globals
// ---------------------------------------------------------------------------
__device__ __align__(16) __nv_bfloat16 g_hhi[2][BSZ * HDIM];
__device__ __align__(16) __nv_bfloat16 g_hlo[2][BSZ * HDIM];
__device__ __align__(16) __nv_bfloat16 g_whi[H3 * HDIM];
__device__ __align__(16) __nv_bfloat16 g_wlo[H3 * HDIM];
__device__ float    g_dotp[TSTEPS * NJB * BSZ];
__device__ unsigned g_bar;

// ---------------------------------------------------------------------------
// PTX helpers (baseline sm_80/90 features only — NO tcgen05)
// ---------------------------------------------------------------------------
__device__ __forceinline__ uint32_t smem_u32(const void* p) {
    uint32_t a;
    asm("{ .reg .u64 t; cvta.to.shared.u64 t, %1; cvt.u32.u64 %0, t; }"
        : "=r"(a) : "l"(p));
    return a;
}
__device__ __forceinline__ void cp16(uint32_t d, const void* s) {
    asm volatile("cp.async.cg.shared.global [%0], [%1], 16;" :: "r"(d), "l"(s));
}
__device__ __forceinline__ void cp_commit() {
    asm volatile("cp.async.commit_group;" ::: "memory");
}
template <int N>
__device__ __forceinline__ void cp_wait() {
    asm volatile("cp.async.wait_group %0;" :: "n"(N) : "memory");
}
__device__ __forceinline__ void ldsm_x4(uint32_t* r, uint32_t a) {
    asm volatile("ldmatrix.sync.aligned.m8n8.x4.shared.b16 {%0,%1,%2,%3}, [%4];"
                 : "=r"(r[0]), "=r"(r[1]), "=r"(r[2]), "=r"(r[3]) : "r"(a));
}
__device__ __forceinline__ void ldsm_x2(uint32_t* r, uint32_t a) {
    asm volatile("ldmatrix.sync.aligned.m8n8.x2.shared.b16 {%0,%1}, [%2];"
                 : "=r"(r[0]), "=r"(r[1]) : "r"(a));
}
__device__ __forceinline__ void mma_bf16(float* c, const uint32_t* a, const uint32_t* b) {
    asm volatile(
        "mma.sync.aligned.m16n8k16.row.col.f32.bf16.bf16.f32 "
        "{%0,%1,%2,%3}, {%4,%5,%6,%7}, {%8,%9}, {%0,%1,%2,%3};"
        : "+f"(c[0]), "+f"(c[1]), "+f"(c[2]), "+f"(c[3])
        : "r"(a[0]), "r"(a[1]), "r"(a[2]), "r"(a[3]), "r"(b[0]), "r"(b[1]));
}
#define SW128(o) ((o) ^ (((o) >> 3) & 0x70))

// ---------------------------------------------------------------------------
// Prep kernels
// ---------------------------------------------------------------------------
__global__ void prep_w_kernel(const float* __restrict__ W) {
    int i = blockIdx.x * blockDim.x + threadIdx.x;
    if (i < H3 * HDIM) {
        float v = W[i];
        __nv_bfloat16 hi = __float2bfloat16_rn(v);
        g_whi[i] = hi;
        g_wlo[i] = __float2bfloat16_rn(v - __bfloat162float(hi));
    }
}
__global__ void prep_h_kernel(const float* __restrict__ ctx) {
    int i = blockIdx.x * blockDim.x + threadIdx.x;
    if (i == 0) g_bar = 0u;
    if (i < BSZ * HDIM) {
        float v = ctx[i];
        __nv_bfloat16 hi = __float2bfloat16_rn(v);
        g_hhi[0][i] = hi;
        g_hlo[0][i] = __float2bfloat16_rn(v - __bfloat162float(hi));
    }
}

// ---------------------------------------------------------------------------
// Grid barrier (96 CTAs, 1/SM, all co-resident)
// ---------------------------------------------------------------------------
__device__ __forceinline__ void grid_barrier(unsigned target) {
    __syncthreads();
    if (threadIdx.x == 0) {
        __threadfence();
        atomicAdd(&g_bar, 1u);
        unsigned v;
        do { v = *(volatile unsigned*)&g_bar; } while (v < target);
        __threadfence();
    }
    __syncthreads();
}

// ---------------------------------------------------------------------------
// Persistent kernel: all 128 GRU steps.
// Grid (48, 2), 512 threads = 16 warps (4/SMSP), warp tile 16x24.
// ---------------------------------------------------------------------------
__global__ __launch_bounds__(NTHREADS, 1) void persist_kernel(
    const float* __restrict__ context,
    const float* __restrict__ bias_ih,
    const float* __restrict__ bias_hh,
    const float* __restrict__ fc_w)
{
    extern __shared__ __align__(16) uint8_t smem[];
    __shared__ float sbr[JT], sbz[JT], sbni[JT], sbnh[JT], sfw[JT];

    const uint32_t sbase = smem_u32(smem);
    const int tid    = threadIdx.x;
    const int lane   = tid & 31;
    const int wid    = tid >> 5;
    const int warp_m = (wid & 7) * 16;     // 8 m-tiles of 16
    const int warp_n = (wid >> 3) * 24;    // 2 n-tiles of 24
    const int jb     = blockIdx.x;
    const int j0     = jb * JT;
    const int brow   = blockIdx.y * MTILE;

    // Epilogue ownership: thread = (batch row, j-quad)
    const int eb = tid >> 2;               // 0..127 batch row within tile
    const int ejq = (tid & 3) * 4;         // j offset 0,4,8,12

    // ---- stage resident W (hi+lo) into SMEM, SW128 swizzled ----
    for (int idx = tid; idx < NCHUNKS * NB * 8; idx += NTHREADS) {
        int ck  = idx / (NB * 8);
        int rem = idx - ck * (NB * 8);
        int r   = rem >> 3, cg = rem & 7;
        int wrow = (r >> 4) * HDIM + j0 + (r & 15);
        size_t so = (size_t)wrow * HDIM + ck * KCHUNK + cg * 8;
        uint32_t dst = (uint32_t)(ck * (NB * 128)) + SW128((uint32_t)(r * 128 + cg * 16));
        cp16(sbase + dst,         g_whi + so);
        cp16(sbase + WPART + dst, g_wlo + so);
    }
    cp_commit();

    if (tid < JT) {
        int j = j0 + tid;
        sbr[tid]  = bias_ih[j] + bias_hh[j];
        sbz[tid]  = bias_ih[HDIM + j] + bias_hh[HDIM + j];
        sbni[tid] = bias_ih[2 * HDIM + j];
        sbnh[tid] = bias_hh[2 * HDIM + j];
        sfw[tid]  = fc_w[j];
    }

    // fp32 h in registers: thread owns (brow+eb, j0+ejq .. +3)
    float hreg[4];
    {
        const float* crow = context + (size_t)(brow + eb) * HDIM + j0 + ejq;
#pragma unroll
        for (int jj = 0; jj < 4; jj++) hreg[jj] = crow[jj];
    }
    __syncthreads();

    unsigned bar_target = 0;
    for (int t = 0; t < TSTEPS; t++) {
        const int rp = t & 1;
        const int wp = rp ^ 1;
        const __nv_bfloat16* __restrict__ hhi = g_hhi[rp];
        const __nv_bfloat16* __restrict__ hlo = g_hlo[rp];

        float acc[3][4];
#pragma unroll
        for (int ni = 0; ni < 3; ni++)
#pragma unroll
            for (int q = 0; q < 4; q++) acc[ni][q] = 0.0f;

        auto issueA = [&](int ck) {
            const int k0 = ck * KCHUNK;
            const uint32_t abase = sbase + AOFF + (uint32_t)(ck & 1) * ABUF;
#pragma unroll
            for (int idx = tid; idx < MTILE * 8; idx += NTHREADS) {  // 2 iters
                int r = idx >> 3, cg = idx & 7;
                uint32_t off = SW128((uint32_t)(r * 128 + cg * 16));
                size_t so = (size_t)(brow + r) * HDIM + k0 + cg * 8;
                cp16(abase + off,         hhi + so);
                cp16(abase + APART + off, hlo + so);
            }
            cp_commit();
        };

        auto compute = [&](int ck) {
            const uint32_t abase = sbase + AOFF + (uint32_t)(ck & 1) * ABUF;
            const uint32_t wbase = sbase + (uint32_t)(ck * (NB * 128));
#pragma unroll
            for (int ks = 0; ks < KCHUNK / 16; ks++) {
                const uint32_t kb = ks * 32;
                uint32_t ah[4], al[4], bh[3][2], bl[3][2];
                {
                    uint32_t off = SW128(
                        (uint32_t)((warp_m + (lane & 15)) * 128) + kb +
                        ((lane >> 4) & 1) * 16);
                    ldsm_x4(ah, abase + off);
                    ldsm_x4(al, abase + APART + off);
                }
#pragma unroll
                for (int ni = 0; ni < 3; ni++) {
                    uint32_t off = SW128(
                        (uint32_t)((warp_n + ni * 8 + (lane & 7)) * 128) + kb +
                        ((lane >> 3) & 1) * 16);
                    ldsm_x2(bh[ni], wbase + off);
                    ldsm_x2(bl[ni], wbase + WPART + off);
                }
#pragma unroll
                for (int ni = 0; ni < 3; ni++) {
                    mma_bf16(acc[ni], ah, bh[ni]);
                    mma_bf16(acc[ni], ah, bl[ni]);
                    mma_bf16(acc[ni], al, bh[ni]);
                }
            }
        };

        issueA(0);
        for (int ck = 0; ck < NCHUNKS; ck++) {
            if (ck + 1 < NCHUNKS) { issueA(ck + 1); cp_wait<1>(); }
            else                  { cp_wait<0>(); }
            __syncthreads();
            compute(ck);
            __syncthreads();
        }

        // ---- C to SMEM (aliases A buffers) ----
        float* Csm = (float*)(smem + AOFF);
        {
            const int r0 = lane >> 2, cpn = (lane & 3) * 2;
#pragma unroll
            for (int ni = 0; ni < 3; ni++) {
                int row = warp_m + r0;
                int col = warp_n + ni * 8 + cpn;
                Csm[row * CSTRIDE + col]           = acc[ni][0];
                Csm[row * CSTRIDE + col + 1]       = acc[ni][1];
                Csm[(row + 8) * CSTRIDE + col]     = acc[ni][2];
                Csm[(row + 8) * CSTRIDE + col + 1] = acc[ni][3];
            }
        }
        __syncthreads();

        // ---- gate epilogue: thread = (batch row, j-quad), 4 j's each ----
        {
            const int b = brow + eb;
            __nv_bfloat16* __restrict__ hih = g_hhi[wp] + (size_t)b * HDIM + j0 + ejq;
            __nv_bfloat16* __restrict__ hil = g_hlo[wp] + (size_t)b * HDIM + j0 + ejq;
            const float* crow = Csm + eb * CSTRIDE;

            float part = 0.0f;
#pragma unroll
            for (int q = 0; q < 4; q++) {
                const int jj = ejq + q;
                float rawr = crow[jj];
                float rawz = crow[JT + jj];
                float rawn = crow[2 * JT + jj];

                float rg = 1.0f / (1.0f + expf(-(sbr[jj] + rawr)));
                float zg = 1.0f / (1.0f + expf(-(sbz[jj] + rawz)));
                float ng = tanhf(sbni[jj] + rg * (rawn + sbnh[jj]));
                float hn = (1.0f - zg) * ng + zg * hreg[q];

                hreg[q] = hn;
                __nv_bfloat16 hi = __float2bfloat16_rn(hn);
                hih[q] = hi;
                hil[q] = __float2bfloat16_rn(hn - __bfloat162float(hi));
                part += hn * sfw[jj];
            }
            // reduce across the 4 threads of this batch row (same warp, aligned quad)
            part += __shfl_xor_sync(0xFFFFFFFFu, part, 1);
            part += __shfl_xor_sync(0xFFFFFFFFu, part, 2);
            if ((tid & 3) == 0)
                g_dotp[(size_t)t * NJB * BSZ + jb * BSZ + b] = part;
        }
        __syncthreads();   // protect Csm/A-buffer reuse by next step's issueA(0)

        bar_target += NCTA;
        if (t + 1 < TSTEPS) grid_barrier(bar_target);
    }
}

// ---------------------------------------------------------------------------
// Finalize: dot = fixed-order sum of 48 partials, softplus, scan, normalize
// ---------------------------------------------------------------------------
__device__ __forceinline__ float softplusf_(float x) {
    return (x > 0.0f) ? (x + log1pf(expf(-x))) : log1pf(expf(x));
}

__global__ __launch_bounds__(TSTEPS) void finalize_kernel(
    const int* __restrict__ num_pred,
    const float* __restrict__ fc_b,
    float* __restrict__ out)
{
    __shared__ float s[TSTEPS];
    const int b = blockIdx.x;
    const int t = threadIdx.x;

    float dot = fc_b[0];
    const float* p = g_dotp + (size_t)t * NJB * BSZ + b;
#pragma unroll
    for (int jbk = 0; jbk < NJB; jbk++) dot += p[jbk * BSZ];
    s[t] = softplusf_(dot);
    __syncthreads();

#pragma unroll
    for (int off = 1; off < TSTEPS; off <<= 1) {
        float v = (t >= off) ? s[t - off] : 0.0f;
        __syncthreads();
        s[t] += v;
        __syncthreads();
    }

    const int n = num_pred[b];
    int idx = n - 1;
    if (idx < 0) idx = 0;
    if (idx > TSTEPS - 1) idx = TSTEPS - 1;
    const float last = s[idx] + 1e-6f;

    float* orow = out + (size_t)b * (TSTEPS + 2);
    float val;
    if (t < n)       val = s[t] / last;
    else if (t == n) val = 1.0f;
    else             val = 0.0f;
    orow[t + 1] = val;

    if (t == 0) {
        orow[0] = 0.0f;
        orow[TSTEPS + 1] = (n == TSTEPS) ? 1.0f : 0.0f;
    }
}

// ---------------------------------------------------------------------------
// Launch. Inputs: 0 context 1 weight_ih(unused) 2 weight_hh 3 bias_ih
//                 4 bias_hh 5 fc_w 6 fc_b 7 num_pred_list 8 max_steps
// ---------------------------------------------------------------------------
extern "C" void kernel_launch(void* const* d_in, const int* in_sizes, int n_in,
                              void* d_out, int out_size)
{
    const float* context  = (const float*)d_in[0];
    const float* Whh      = (const float*)d_in[2];
    const float* bias_ih  = (const float*)d_in[3];
    const float* bias_hh  = (const float*)d_in[4];
    const float* fc_w     = (const float*)d_in[5];
    const float* fc_b     = (const float*)d_in[6];
    const int*   num_pred = (const int*)d_in[7];
    float*       out      = (float*)d_out;

    static bool attr_set = false;
    if (!attr_set) {
        cudaFuncSetAttribute(persist_kernel,
                             cudaFuncAttributeMaxDynamicSharedMemorySize, SMEM_DYN);
        attr_set = true;
    }

    prep_w_kernel<<<(H3 * HDIM + 255) / 256, 256>>>(Whh);
    prep_h_kernel<<<(BSZ * HDIM + 255) / 256, 256>>>(context);

    dim3 grid(NJB, BSZ / MTILE);  // (48, 2) = 96 CTAs, 1 per SM
    persist_kernel<<<grid, NTHREADS, SMEM_DYN>>>(context, bias_ih, bias_hh, fc_w);

    finalize_kernel<<<BSZ, TSTEPS>>>(num_pred, fc_b, out);
}